// round 12
// baseline (speedup 1.0000x reference)
#include <cuda_runtime.h>

#define NN 512
#define PP 130816
typedef unsigned long long ull;

__device__ float g_ca[NN*512];
__device__ float g_cb[NN*512];
__device__ float g_sa[NN*256];
__device__ float g_sb[NN*256];
__device__ float g_ca2[NN*512];
__device__ float g_cb2[NN*512];
__device__ float g_sa2[NN*256];
__device__ float g_sb2[NN*256];

__device__ __forceinline__ ull pack2(float lo, float hi) {
    ull r; asm("mov.b64 %0, {%1, %2};" : "=l"(r) : "f"(lo), "f"(hi)); return r;
}
__device__ __forceinline__ void fma2(ull& d, ull a, ull b) {
    asm("fma.rn.f32x2 %0, %1, %2, %0;" : "+l"(d) : "l"(a), "l"(b));
}
__device__ __forceinline__ ull add2(ull a, ull b) {
    ull r; asm("add.rn.f32x2 %0, %1, %2;" : "=l"(r) : "l"(a), "l"(b)); return r;
}
__device__ __forceinline__ float2 unpack2(ull v) {
    float2 f; asm("mov.b64 {%0, %1}, %2;" : "=f"(f.x), "=f"(f.y) : "l"(v)); return f;
}

// ---------------------------------------------------------------------------
// Phase 1: K-SPLIT proj GEMM. grid (24, 8, 2): z = K-half.
// Each block: BM=64, BN=64, K=256 (8 tiles of BK=32), 256 threads.
// Half 0 writes g_*, half 1 writes g_*2; pair staging sums them.
// ---------------------------------------------------------------------------
__global__ __launch_bounds__(256) void proj_gemm(const float* __restrict__ F,
                                                 const float* __restrict__ cw1,
                                                 const float* __restrict__ sw1) {
    __shared__ __align__(16) float As[32 * 68];
    __shared__ __align__(16) ull  Bs[32 * 64];
    int t = threadIdx.x;
    int ks = blockIdx.z;
    int cglob = blockIdx.x * 64;
    const float* Bp; float* Cp; int ldb, bcol;
    if (cglob < 512)       { Bp = cw1;             Cp = ks ? g_ca2 : g_ca; ldb = 512; bcol = cglob; }
    else if (cglob < 1024) { Bp = cw1 + 512 * 512; Cp = ks ? g_cb2 : g_cb; ldb = 512; bcol = cglob - 512; }
    else if (cglob < 1280) { Bp = sw1;             Cp = ks ? g_sa2 : g_sa; ldb = 256; bcol = cglob - 1024; }
    else                   { Bp = sw1 + 512 * 256; Cp = ks ? g_sb2 : g_sb; ldb = 256; bcol = cglob - 1280; }
    int rb = blockIdx.y * 64;
    int kbase = ks * 256;
    int rowg = t & 15, colg = t >> 4;

    ull acc[2][4];
#pragma unroll
    for (int a = 0; a < 2; a++)
#pragma unroll
        for (int b = 0; b < 4; b++) acc[a][b] = 0ull;

    for (int tile = 0; tile < 8; tile++) {
        int k0 = kbase + tile * 32;
#pragma unroll
        for (int it = 0; it < 2; it++) {
            int idx = t + it * 256, row = idx >> 3, q8 = idx & 7;
            float4 v = *(const float4*)&F[(rb + row) * 512 + k0 + q8 * 4];
            As[(q8 * 4 + 0) * 68 + row] = v.x;
            As[(q8 * 4 + 1) * 68 + row] = v.y;
            As[(q8 * 4 + 2) * 68 + row] = v.z;
            As[(q8 * 4 + 3) * 68 + row] = v.w;
        }
#pragma unroll
        for (int it = 0; it < 2; it++) {
            int idx = t + it * 256, k = idx >> 4, q16 = idx & 15;
            float4 v = *(const float4*)&Bp[(k0 + k) * ldb + bcol + q16 * 4];
            Bs[k * 64 + q16 * 4 + 0] = pack2(v.x, v.x);
            Bs[k * 64 + q16 * 4 + 1] = pack2(v.y, v.y);
            Bs[k * 64 + q16 * 4 + 2] = pack2(v.z, v.z);
            Bs[k * 64 + q16 * 4 + 3] = pack2(v.w, v.w);
        }
        __syncthreads();
#pragma unroll
        for (int k = 0; k < 32; k++) {
            ulonglong2 aA = *(const ulonglong2*)&As[k * 68 + rowg * 4];
            ulonglong2 b0 = *(const ulonglong2*)&Bs[k * 64 + colg * 4];
            ulonglong2 b1 = *(const ulonglong2*)&Bs[k * 64 + colg * 4 + 2];
            fma2(acc[0][0], aA.x, b0.x); fma2(acc[0][1], aA.x, b0.y);
            fma2(acc[0][2], aA.x, b1.x); fma2(acc[0][3], aA.x, b1.y);
            fma2(acc[1][0], aA.y, b0.x); fma2(acc[1][1], aA.y, b0.y);
            fma2(acc[1][2], aA.y, b1.x); fma2(acc[1][3], aA.y, b1.y);
        }
        __syncthreads();
    }
#pragma unroll
    for (int mp = 0; mp < 2; mp++) {
        int r = rb + rowg * 4 + mp * 2;
#pragma unroll
        for (int n = 0; n < 4; n++) {
            float2 f = unpack2(acc[mp][n]);
            int c = bcol + colg * 4 + n;
            Cp[r * ldb + c] = f.x;
            Cp[(r + 1) * ldb + c] = f.y;
        }
    }
}

// ---------------------------------------------------------------------------
// Phase 2: 512 threads = 16 warps, tile 32j x 32i. 4 PAIRS/LANE + K-SPLIT:
// wg = w&7 owns i = 4wg..4wg+3; half = w>>3 covers k in [half*256, +256).
// K-paired h packing (zero pack MOVs for h inputs), cw2 as kp-pair table.
// smem floats: bC 32x516 (cb1+both proj halves folded) | aC 32x512 | wp 2560 ull.
// Strength overlays; k-half reduction through smem at the end.
// ---------------------------------------------------------------------------
#define O_BC 0
#define O_AC 16512
#define O_WP 32896
#define SMEMF 38016

__global__ __launch_bounds__(512) void pair_kernel(
    const float* __restrict__ cb1, const float* __restrict__ cw2,
    const float* __restrict__ cb2, const float* __restrict__ sb1,
    const float* __restrict__ sw2, const float* __restrict__ sb2,
    float* __restrict__ out)
{
    extern __shared__ float sm[];
    int bid = blockIdx.x;
    int jb = (int)((sqrtf(8.0f * bid + 1.0f) - 1.0f) * 0.5f);
    while ((jb + 1) * (jb + 2) / 2 <= bid) jb++;
    while (jb * (jb + 1) / 2 > bid) jb--;
    int ib = bid - jb * (jb + 1) / 2;
    int jbase = jb * 32, ibase = ib * 32;
    int t = threadIdx.x;
    int w = t >> 5, lane = t & 31;
    int wg = w & 7, half = w >> 3;

    // stage bC = g_cb + g_cb2 + cb1
#pragma unroll
    for (int it = 0; it < 8; it++) {
        int idx = t + it * 512;
        int r = idx >> 7, q = (idx & 127) * 4;
        float4 v1 = *(const float4*)&g_cb[(jbase + r) * 512 + q];
        float4 v2 = *(const float4*)&g_cb2[(jbase + r) * 512 + q];
        float4 vc = *(const float4*)&cb1[q];
        v1.x += v2.x + vc.x; v1.y += v2.y + vc.y;
        v1.z += v2.z + vc.z; v1.w += v2.w + vc.w;
        *(float4*)&sm[O_BC + r * 516 + q] = v1;
    }
    // stage aC = g_ca + g_ca2
#pragma unroll
    for (int it = 0; it < 8; it++) {
        int idx = t + it * 512;
        int r = idx >> 7, q = (idx & 127) * 4;
        float4 v1 = *(const float4*)&g_ca[(ibase + r) * 512 + q];
        float4 v2 = *(const float4*)&g_ca2[(ibase + r) * 512 + q];
        v1.x += v2.x; v1.y += v2.y; v1.z += v2.z; v1.w += v2.w;
        *(float4*)&sm[O_AC + r * 512 + q] = v1;
    }
    // wp: kp-paired cw2
    {
        ull* wp = (ull*)&sm[O_WP];
        for (int idx = t; idx < 2560; idx += 512) {
            int kp = idx / 10, c = idx - kp * 10;
            wp[idx] = pack2(cw2[kp * 20 + c], cw2[kp * 20 + 10 + c]);
        }
    }
    __syncthreads();

    const float* bRow = &sm[O_BC + lane * 516];
    const float* aR0 = &sm[O_AC + (4 * wg + 0) * 512];
    const float* aR1 = aR0 + 512;
    const float* aR2 = aR0 + 1024;
    const float* aR3 = aR0 + 1536;
    const ull*   wp  = (const ull*)&sm[O_WP];

    ull acc0[10], acc1[10], acc2[10], acc3[10];
#pragma unroll
    for (int c = 0; c < 10; c++) { acc0[c] = 0; acc1[c] = 0; acc2[c] = 0; acc3[c] = 0; }

    int koff = half * 256;
    for (int k0 = koff; k0 < koff + 256; k0 += 4) {
        ulonglong2 bp = *(const ulonglong2*)(bRow + k0);
        ulonglong2 a0 = *(const ulonglong2*)(aR0 + k0);
        ulonglong2 a1 = *(const ulonglong2*)(aR1 + k0);
        ulonglong2 a2 = *(const ulonglong2*)(aR2 + k0);
        ulonglong2 a3 = *(const ulonglong2*)(aR3 + k0);
        float2 f;
        f = unpack2(add2(a0.x, bp.x)); ull h0A = pack2(fmaxf(f.x,0.f), fmaxf(f.y,0.f));
        f = unpack2(add2(a0.y, bp.y)); ull h0B = pack2(fmaxf(f.x,0.f), fmaxf(f.y,0.f));
        f = unpack2(add2(a1.x, bp.x)); ull h1A = pack2(fmaxf(f.x,0.f), fmaxf(f.y,0.f));
        f = unpack2(add2(a1.y, bp.y)); ull h1B = pack2(fmaxf(f.x,0.f), fmaxf(f.y,0.f));
        f = unpack2(add2(a2.x, bp.x)); ull h2A = pack2(fmaxf(f.x,0.f), fmaxf(f.y,0.f));
        f = unpack2(add2(a2.y, bp.y)); ull h2B = pack2(fmaxf(f.x,0.f), fmaxf(f.y,0.f));
        f = unpack2(add2(a3.x, bp.x)); ull h3A = pack2(fmaxf(f.x,0.f), fmaxf(f.y,0.f));
        f = unpack2(add2(a3.y, bp.y)); ull h3B = pack2(fmaxf(f.x,0.f), fmaxf(f.y,0.f));
        const ulonglong2* wA = (const ulonglong2*)(wp + (k0 >> 1) * 10);
        const ulonglong2* wB = (const ulonglong2*)(wp + (k0 >> 1) * 10 + 10);
#pragma unroll
        for (int q = 0; q < 5; q++) {
            ulonglong2 wa = wA[q];
            fma2(acc0[2*q], h0A, wa.x); fma2(acc0[2*q+1], h0A, wa.y);
            fma2(acc1[2*q], h1A, wa.x); fma2(acc1[2*q+1], h1A, wa.y);
            fma2(acc2[2*q], h2A, wa.x); fma2(acc2[2*q+1], h2A, wa.y);
            fma2(acc3[2*q], h3A, wa.x); fma2(acc3[2*q+1], h3A, wa.y);
            ulonglong2 wb = wB[q];
            fma2(acc0[2*q], h0B, wb.x); fma2(acc0[2*q+1], h0B, wb.y);
            fma2(acc1[2*q], h1B, wb.x); fma2(acc1[2*q+1], h1B, wb.y);
            fma2(acc2[2*q], h2B, wb.x); fma2(acc2[2*q+1], h2B, wb.y);
            fma2(acc3[2*q], h3B, wb.x); fma2(acc3[2*q+1], h3B, wb.y);
        }
    }

    // ---- strength path: overlay same smem ----
    __syncthreads();
#pragma unroll
    for (int it = 0; it < 4; it++) {   // bS 32x260 = g_sb + g_sb2 + sb1
        int idx = t + it * 512;
        int r = idx >> 6, q = (idx & 63) * 4;
        float4 v1 = *(const float4*)&g_sb[(jbase + r) * 256 + q];
        float4 v2 = *(const float4*)&g_sb2[(jbase + r) * 256 + q];
        float4 vc = *(const float4*)&sb1[q];
        v1.x += v2.x + vc.x; v1.y += v2.y + vc.y;
        v1.z += v2.z + vc.z; v1.w += v2.w + vc.w;
        *(float4*)&sm[O_BC + r * 260 + q] = v1;
    }
#pragma unroll
    for (int it = 0; it < 4; it++) {   // aS 32x256 = g_sa + g_sa2
        int idx = t + it * 512;
        int r = idx >> 6, q = (idx & 63) * 4;
        float4 v1 = *(const float4*)&g_sa[(ibase + r) * 256 + q];
        float4 v2 = *(const float4*)&g_sa2[(ibase + r) * 256 + q];
        v1.x += v2.x; v1.y += v2.y; v1.z += v2.z; v1.w += v2.w;
        *(float4*)&sm[O_AC + r * 256 + q] = v1;
    }
    if (t < 128) ((ull*)&sm[O_WP])[t] = pack2(sw2[2 * t], sw2[2 * t + 1]);
    __syncthreads();

    ull sc0 = 0, sc1 = 0, sc2 = 0, sc3 = 0;
    {
        const float* sbRow = &sm[O_BC + lane * 260];
        const float* sR0 = &sm[O_AC + (4 * wg + 0) * 256];
        const float* sR1 = sR0 + 256;
        const float* sR2 = sR0 + 512;
        const float* sR3 = sR0 + 768;
        const ull* swp = (const ull*)&sm[O_WP];
        int koff2 = half * 128;
        for (int k0 = koff2; k0 < koff2 + 128; k0 += 4) {
            ulonglong2 bp = *(const ulonglong2*)(sbRow + k0);
            ulonglong2 a0 = *(const ulonglong2*)(sR0 + k0);
            ulonglong2 a1 = *(const ulonglong2*)(sR1 + k0);
            ulonglong2 a2 = *(const ulonglong2*)(sR2 + k0);
            ulonglong2 a3 = *(const ulonglong2*)(sR3 + k0);
            ulonglong2 ww = *(const ulonglong2*)(swp + (k0 >> 1));
            float2 f;
            f = unpack2(add2(a0.x, bp.x)); fma2(sc0, pack2(fmaxf(f.x,0.f), fmaxf(f.y,0.f)), ww.x);
            f = unpack2(add2(a0.y, bp.y)); fma2(sc0, pack2(fmaxf(f.x,0.f), fmaxf(f.y,0.f)), ww.y);
            f = unpack2(add2(a1.x, bp.x)); fma2(sc1, pack2(fmaxf(f.x,0.f), fmaxf(f.y,0.f)), ww.x);
            f = unpack2(add2(a1.y, bp.y)); fma2(sc1, pack2(fmaxf(f.x,0.f), fmaxf(f.y,0.f)), ww.y);
            f = unpack2(add2(a2.x, bp.x)); fma2(sc2, pack2(fmaxf(f.x,0.f), fmaxf(f.y,0.f)), ww.x);
            f = unpack2(add2(a2.y, bp.y)); fma2(sc2, pack2(fmaxf(f.x,0.f), fmaxf(f.y,0.f)), ww.y);
            f = unpack2(add2(a3.x, bp.x)); fma2(sc3, pack2(fmaxf(f.x,0.f), fmaxf(f.y,0.f)), ww.x);
            f = unpack2(add2(a3.y, bp.y)); fma2(sc3, pack2(fmaxf(f.x,0.f), fmaxf(f.y,0.f)), ww.y);
        }
    }

    // ---- k-half reduction: half=1 stores 44 ulls per (wg,lane), half=0 sums ----
    __syncthreads();
    ull* red = (ull*)sm;
    int rbase = wg * 44 * 32 + lane;
    if (half == 1) {
#pragma unroll
        for (int c = 0; c < 10; c++) {
            red[rbase + c * 32]        = acc0[c];
            red[rbase + (10 + c) * 32] = acc1[c];
            red[rbase + (20 + c) * 32] = acc2[c];
            red[rbase + (30 + c) * 32] = acc3[c];
        }
        red[rbase + 40 * 32] = sc0;
        red[rbase + 41 * 32] = sc1;
        red[rbase + 42 * 32] = sc2;
        red[rbase + 43 * 32] = sc3;
    }
    __syncthreads();

    if (half == 0) {
#pragma unroll
        for (int c = 0; c < 10; c++) {
            acc0[c] = add2(acc0[c], red[rbase + c * 32]);
            acc1[c] = add2(acc1[c], red[rbase + (10 + c) * 32]);
            acc2[c] = add2(acc2[c], red[rbase + (20 + c) * 32]);
            acc3[c] = add2(acc3[c], red[rbase + (30 + c) * 32]);
        }
        sc0 = add2(sc0, red[rbase + 40 * 32]);
        sc1 = add2(sc1, red[rbase + 41 * 32]);
        sc2 = add2(sc2, red[rbase + 42 * 32]);
        sc3 = add2(sc3, red[rbase + 43 * 32]);

        int j = jbase + lane;
        float b2[10];
#pragma unroll
        for (int c = 0; c < 10; c++) b2[c] = __ldg(&cb2[c]);
        float sbv = __ldg(&sb2[0]);
#pragma unroll
        for (int s = 0; s < 4; s++) {
            int i = ibase + 4 * wg + s;
            if (j <= i) continue;
            const ull* ac = (s == 0) ? acc0 : (s == 1) ? acc1 : (s == 2) ? acc2 : acc3;
            ull scv = (s == 0) ? sc0 : (s == 1) ? sc1 : (s == 2) ? sc2 : sc3;
            float l[10];
#pragma unroll
            for (int c = 0; c < 10; c++) {
                float2 f = unpack2(ac[c]);
                l[c] = f.x + f.y + b2[c];
            }
            float m = l[0]; int idx = 0;
#pragma unroll
            for (int c = 1; c < 10; c++) if (l[c] > m) { m = l[c]; idx = c; }
            float sum = 0.f;
#pragma unroll
            for (int c = 0; c < 10; c++) sum += __expf(l[c] - m);
            float lse = m + __logf(sum);
            int p = i * (1023 - i) / 2 + j - i - 1;
            float2* o2 = (float2*)(out + (size_t)p * 10);
#pragma unroll
            for (int q = 0; q < 5; q++)
                o2[q] = make_float2(l[2 * q] - lse, l[2 * q + 1] - lse);
            out[10 * PP + p] = (float)idx;
            float2 fs = unpack2(scv);
            float x = fs.x + fs.y + sbv;
            out[11 * PP + p] = 1.f / (1.f + __expf(-x));
        }
    }
}

extern "C" void kernel_launch(void* const* d_in, const int* in_sizes, int n_in,
                              void* d_out, int out_size) {
    (void)in_sizes; (void)n_in; (void)out_size;
    const float* features = (const float*)d_in[0];
    const float* cw1 = (const float*)d_in[1];
    const float* cb1 = (const float*)d_in[2];
    const float* cw2 = (const float*)d_in[3];
    const float* cb2 = (const float*)d_in[4];
    const float* sw1 = (const float*)d_in[5];
    const float* sb1 = (const float*)d_in[6];
    const float* sw2 = (const float*)d_in[7];
    const float* sb2 = (const float*)d_in[8];
    float* out = (float*)d_out;

    cudaFuncSetAttribute(pair_kernel, cudaFuncAttributeMaxDynamicSharedMemorySize,
                         SMEMF * sizeof(float));

    proj_gemm<<<dim3(24, 8, 2), 256>>>(features, cw1, sw1);
    pair_kernel<<<136, 512, SMEMF * sizeof(float)>>>(
        cb1, cw2, cb2, sb1, sw2, sb2, out);
}